// round 15
// baseline (speedup 1.0000x reference)
#include <cuda_runtime.h>

// SmallRNN: h_t = tanh(x_t * w_ih^T + b_ih + h_{t-1} * w_hh^T + b_hh), out = h_T @ fc_w^T + fc_b
// Shapes: x [B=4096, T=2048, I=1], w_ih [8,1], w_hh [8,8], b_* [8], fc_w [1,8], fc_b [1]
//
// R13 = banked R6 (90.6us) with EXACTLY ONE change: the vectorized loop in
// run_range unrolls 16 steps per iteration instead of 8 (halves the per-step
// share of branch + predicated-prefetch-mux overhead). Step body, memory
// clobbers, FMA-tree shape, tanh.approx main + exact ex2+rcp 64-step tail,
// and launch config are byte-identical to the reproduced best.

#define TBLOCK 256
#define EXACT_TAIL 64

__device__ __forceinline__ float ex2f(float x) {
    float y; asm("ex2.approx.f32 %0, %1;" : "=f"(y) : "f"(x)); return y;
}
__device__ __forceinline__ float rcpf(float x) {
    float y; asm("rcp.approx.f32 %0, %1;" : "=f"(y) : "f"(x)); return y;
}
__device__ __forceinline__ float tanhf_approx(float x) {
    float y; asm("tanh.approx.f32 %0, %1;" : "=f"(y) : "f"(x)); return y;
}

template <bool EXACT>
__device__ __forceinline__ float rnn_step(float h, float xv,
                                          unsigned own_addr, unsigned vec_addr,
                                          const float w[8], float Bj, float wih) {
    // publish own h, then fetch the group's 8 values; asm volatile + memory
    // clobber pins ST->LD ordering (per-warp in-order smem LSU does the rest).
    asm volatile("st.shared.f32 [%0], %1;" :: "r"(own_addr), "f"(h) : "memory");
    float v0, v1, v2, v3, v4, v5, v6, v7;
    asm volatile("ld.shared.v4.f32 {%0,%1,%2,%3}, [%4];"
                 : "=f"(v0), "=f"(v1), "=f"(v2), "=f"(v3)
                 : "r"(vec_addr) : "memory");
    asm volatile("ld.shared.v4.f32 {%0,%1,%2,%3}, [%4];"
                 : "=f"(v4), "=f"(v5), "=f"(v6), "=f"(v7)
                 : "r"(vec_addr + 16u) : "memory");
    // 4-way split FMA tree, then combine; x-term and bias are off-chain
    float a = fmaf(xv, wih, Bj);
    a = fmaf(v0, w[0], a);
    float b = v1 * w[1];
    float cc = v2 * w[2];
    float d = v3 * w[3];
    a  = fmaf(v4, w[4], a);
    b  = fmaf(v5, w[5], b);
    cc = fmaf(v6, w[6], cc);
    d  = fmaf(v7, w[7], d);
    float s = (a + b) + (cc + d);
    if (EXACT) {
        const float c2 = 2.8853900817779268f; // 2*log2(e)
        float e = ex2f(c2 * s);
        float r = rcpf(e + 1.0f);
        return fmaf(-2.0f, r, 1.0f); // tanh(s) = 1 - 2*sigmoid(-2s)
    } else {
        return tanhf_approx(s);
    }
}

template <bool EXACT>
__device__ __forceinline__ float run_range(float h, const float* __restrict__ xp,
                                           int t0, int t1,
                                           unsigned own_addr, unsigned vec_addr,
                                           const float w[8], float Bj, float wih) {
    int span = t1 - t0;
    int Tm = span & ~15;
    const float* p = xp + t0;
    if (((unsigned long long)p & 15ull) == 0ull && Tm > 0) {
        float4 xa  = *(const float4*)(p);
        float4 xb_ = *(const float4*)(p + 4);
        float4 xc  = *(const float4*)(p + 8);
        float4 xd  = *(const float4*)(p + 12);
        for (int t = 0; t < Tm; t += 16) {
            float4 n0, n1, n2, n3;
            if (t + 16 < Tm) {
                n0 = *(const float4*)(p + t + 16);
                n1 = *(const float4*)(p + t + 20);
                n2 = *(const float4*)(p + t + 24);
                n3 = *(const float4*)(p + t + 28);
            } else {
                n0 = make_float4(0.f, 0.f, 0.f, 0.f);
                n1 = n0; n2 = n0; n3 = n0;
            }
            h = rnn_step<EXACT>(h, xa.x,  own_addr, vec_addr, w, Bj, wih);
            h = rnn_step<EXACT>(h, xa.y,  own_addr, vec_addr, w, Bj, wih);
            h = rnn_step<EXACT>(h, xa.z,  own_addr, vec_addr, w, Bj, wih);
            h = rnn_step<EXACT>(h, xa.w,  own_addr, vec_addr, w, Bj, wih);
            h = rnn_step<EXACT>(h, xb_.x, own_addr, vec_addr, w, Bj, wih);
            h = rnn_step<EXACT>(h, xb_.y, own_addr, vec_addr, w, Bj, wih);
            h = rnn_step<EXACT>(h, xb_.z, own_addr, vec_addr, w, Bj, wih);
            h = rnn_step<EXACT>(h, xb_.w, own_addr, vec_addr, w, Bj, wih);
            h = rnn_step<EXACT>(h, xc.x,  own_addr, vec_addr, w, Bj, wih);
            h = rnn_step<EXACT>(h, xc.y,  own_addr, vec_addr, w, Bj, wih);
            h = rnn_step<EXACT>(h, xc.z,  own_addr, vec_addr, w, Bj, wih);
            h = rnn_step<EXACT>(h, xc.w,  own_addr, vec_addr, w, Bj, wih);
            h = rnn_step<EXACT>(h, xd.x,  own_addr, vec_addr, w, Bj, wih);
            h = rnn_step<EXACT>(h, xd.y,  own_addr, vec_addr, w, Bj, wih);
            h = rnn_step<EXACT>(h, xd.z,  own_addr, vec_addr, w, Bj, wih);
            h = rnn_step<EXACT>(h, xd.w,  own_addr, vec_addr, w, Bj, wih);
            xa = n0; xb_ = n1; xc = n2; xd = n3;
        }
    } else {
        Tm = 0;
    }
    for (int t = t0 + Tm; t < t1; t++) {
        h = rnn_step<EXACT>(h, xp[t], own_addr, vec_addr, w, Bj, wih);
    }
    return h;
}

__global__ void __launch_bounds__(TBLOCK)
SmallRNN_kernel(const float* __restrict__ x,
                const float* __restrict__ w_ih,
                const float* __restrict__ w_hh,
                const float* __restrict__ b_ih,
                const float* __restrict__ b_hh,
                const float* __restrict__ fc_w,
                const float* __restrict__ fc_b,
                float* __restrict__ out,
                int B, int T) {
    __shared__ float sh[TBLOCK];

    int tx = threadIdx.x;
    int gtid = blockIdx.x * TBLOCK + tx;
    int b_raw = gtid >> 3;     // batch element
    int j = gtid & 7;          // hidden unit owned by this lane
    int b = (b_raw < B) ? b_raw : (B - 1);  // keep lanes active

    unsigned own_addr = (unsigned)__cvta_generic_to_shared(sh + tx);
    unsigned vec_addr = (unsigned)__cvta_generic_to_shared(sh + (tx & ~7));

    float w[8];
#pragma unroll
    for (int k = 0; k < 8; k++) w[k] = w_hh[j * 8 + k];
    float Bj  = b_ih[j] + b_hh[j];
    float wih = w_ih[j];

    const float* xp = x + (size_t)b * (size_t)T;
    float h = 0.0f; // h0 = 0

    int Tmain = T - EXACT_TAIL;
    if (Tmain < 0) Tmain = 0;

    h = run_range<false>(h, xp, 0, Tmain, own_addr, vec_addr, w, Bj, wih);
    h = run_range<true >(h, xp, Tmain, T, own_addr, vec_addr, w, Bj, wih);

    // out[b] = sum_j h_j * fc_w[j] + fc_b
    float v = h * fc_w[j];
    v += __shfl_xor_sync(0xffffffffu, v, 4, 8);
    v += __shfl_xor_sync(0xffffffffu, v, 2, 8);
    v += __shfl_xor_sync(0xffffffffu, v, 1, 8);
    if (j == 0 && b_raw < B) out[b] = v + fc_b[0];
}

extern "C" void kernel_launch(void* const* d_in, const int* in_sizes, int n_in,
                              void* d_out, int out_size) {
    const float* x    = (const float*)d_in[0];
    const float* w_ih = (const float*)d_in[1];
    const float* w_hh = (const float*)d_in[2];
    const float* b_ih = (const float*)d_in[3];
    const float* b_hh = (const float*)d_in[4];
    const float* fc_w = (const float*)d_in[5];
    const float* fc_b = (const float*)d_in[6];
    float* out = (float*)d_out;

    int B = out_size;                 // O = 1
    int T = in_sizes[0] / B;          // I = 1
    int threads = B * 8;
    int grid = (threads + TBLOCK - 1) / TBLOCK;
    SmallRNN_kernel<<<grid, TBLOCK>>>(x, w_ih, w_hh, b_ih, b_hh, fc_w, fc_b,
                                      out, B, T);
}

// round 16
// speedup vs baseline: 1.1105x; 1.1105x over previous
#include <cuda_runtime.h>

// SmallRNN: h_t = tanh(x_t * w_ih^T + b_ih + h_{t-1} * w_hh^T + b_hh), out = h_T @ fc_w^T + fc_b
// Shapes: x [B=4096, T=2048, I=1], w_ih [8,1], w_hh [8,8], b_* [8], fc_w [1,8], fc_b [1]
//
// FINAL (= R6, best measured: 90.6us, reproduced 91.2us, rel_err 1.76e-7):
// 8 lanes per batch element (lane j owns h_j) — keeps chain MUFU count at 1.
// Exchange via shared memory: asm-pinned STS.32 -> 2x LDS.128 (broadcast,
// conflict-free); memory clobbers required (compiler reorders without them;
// removing them also regresses the schedule).
// Activation: tanh.approx.f32 for the first T-64 steps; exact ex2+rcp tanh for
// the last 64 steps. The recurrence contracts, so approx error from early
// steps is suppressed below fp32 rounding by the exact tail.
// Eight structural/scheduling variants measured slower (shuffle exchange,
// lane repacking, FFMA2 single-thread, element pairing lockstep and
// phase-offset, clobber removal, tree reshaping, unroll-16): this source
// elicits the best ptxas schedule and sits at the dependency-chain floor
// of the algorithm on sm_103a (~84 cyc/step: LDS visibility ~35 + tree 16
// + MUFU 16 + latch/loop ~17).

#define TBLOCK 256
#define EXACT_TAIL 64

__device__ __forceinline__ float ex2f(float x) {
    float y; asm("ex2.approx.f32 %0, %1;" : "=f"(y) : "f"(x)); return y;
}
__device__ __forceinline__ float rcpf(float x) {
    float y; asm("rcp.approx.f32 %0, %1;" : "=f"(y) : "f"(x)); return y;
}
__device__ __forceinline__ float tanhf_approx(float x) {
    float y; asm("tanh.approx.f32 %0, %1;" : "=f"(y) : "f"(x)); return y;
}

template <bool EXACT>
__device__ __forceinline__ float rnn_step(float h, float xv,
                                          unsigned own_addr, unsigned vec_addr,
                                          const float w[8], float Bj, float wih) {
    // publish own h, then fetch the group's 8 values; asm volatile + memory
    // clobber pins ST->LD ordering (per-warp in-order smem LSU does the rest).
    asm volatile("st.shared.f32 [%0], %1;" :: "r"(own_addr), "f"(h) : "memory");
    float v0, v1, v2, v3, v4, v5, v6, v7;
    asm volatile("ld.shared.v4.f32 {%0,%1,%2,%3}, [%4];"
                 : "=f"(v0), "=f"(v1), "=f"(v2), "=f"(v3)
                 : "r"(vec_addr) : "memory");
    asm volatile("ld.shared.v4.f32 {%0,%1,%2,%3}, [%4];"
                 : "=f"(v4), "=f"(v5), "=f"(v6), "=f"(v7)
                 : "r"(vec_addr + 16u) : "memory");
    // 4-way split FMA tree, then combine; x-term and bias are off-chain
    float a = fmaf(xv, wih, Bj);
    a = fmaf(v0, w[0], a);
    float b = v1 * w[1];
    float cc = v2 * w[2];
    float d = v3 * w[3];
    a  = fmaf(v4, w[4], a);
    b  = fmaf(v5, w[5], b);
    cc = fmaf(v6, w[6], cc);
    d  = fmaf(v7, w[7], d);
    float s = (a + b) + (cc + d);
    if (EXACT) {
        const float c2 = 2.8853900817779268f; // 2*log2(e)
        float e = ex2f(c2 * s);
        float r = rcpf(e + 1.0f);
        return fmaf(-2.0f, r, 1.0f); // tanh(s) = 1 - 2*sigmoid(-2s)
    } else {
        return tanhf_approx(s);
    }
}

template <bool EXACT>
__device__ __forceinline__ float run_range(float h, const float* __restrict__ xp,
                                           int t0, int t1,
                                           unsigned own_addr, unsigned vec_addr,
                                           const float w[8], float Bj, float wih) {
    int span = t1 - t0;
    int Tm = span & ~7;
    const float* p = xp + t0;
    if (((unsigned long long)p & 15ull) == 0ull && Tm > 0) {
        float4 xa = *(const float4*)(p);
        float4 xb_ = *(const float4*)(p + 4);
        for (int t = 0; t < Tm; t += 8) {
            float4 xn0, xn1;
            if (t + 8 < Tm) {
                xn0 = *(const float4*)(p + t + 8);
                xn1 = *(const float4*)(p + t + 12);
            } else {
                xn0 = make_float4(0.f, 0.f, 0.f, 0.f);
                xn1 = xn0;
            }
            h = rnn_step<EXACT>(h, xa.x,  own_addr, vec_addr, w, Bj, wih);
            h = rnn_step<EXACT>(h, xa.y,  own_addr, vec_addr, w, Bj, wih);
            h = rnn_step<EXACT>(h, xa.z,  own_addr, vec_addr, w, Bj, wih);
            h = rnn_step<EXACT>(h, xa.w,  own_addr, vec_addr, w, Bj, wih);
            h = rnn_step<EXACT>(h, xb_.x, own_addr, vec_addr, w, Bj, wih);
            h = rnn_step<EXACT>(h, xb_.y, own_addr, vec_addr, w, Bj, wih);
            h = rnn_step<EXACT>(h, xb_.z, own_addr, vec_addr, w, Bj, wih);
            h = rnn_step<EXACT>(h, xb_.w, own_addr, vec_addr, w, Bj, wih);
            xa  = xn0;
            xb_ = xn1;
        }
    } else {
        Tm = 0;
    }
    for (int t = t0 + Tm; t < t1; t++) {
        h = rnn_step<EXACT>(h, xp[t], own_addr, vec_addr, w, Bj, wih);
    }
    return h;
}

__global__ void __launch_bounds__(TBLOCK)
SmallRNN_kernel(const float* __restrict__ x,
                const float* __restrict__ w_ih,
                const float* __restrict__ w_hh,
                const float* __restrict__ b_ih,
                const float* __restrict__ b_hh,
                const float* __restrict__ fc_w,
                const float* __restrict__ fc_b,
                float* __restrict__ out,
                int B, int T) {
    __shared__ float sh[TBLOCK];

    int tx = threadIdx.x;
    int gtid = blockIdx.x * TBLOCK + tx;
    int b_raw = gtid >> 3;     // batch element
    int j = gtid & 7;          // hidden unit owned by this lane
    int b = (b_raw < B) ? b_raw : (B - 1);  // keep lanes active

    unsigned own_addr = (unsigned)__cvta_generic_to_shared(sh + tx);
    unsigned vec_addr = (unsigned)__cvta_generic_to_shared(sh + (tx & ~7));

    float w[8];
#pragma unroll
    for (int k = 0; k < 8; k++) w[k] = w_hh[j * 8 + k];
    float Bj  = b_ih[j] + b_hh[j];
    float wih = w_ih[j];

    const float* xp = x + (size_t)b * (size_t)T;
    float h = 0.0f; // h0 = 0

    int Tmain = T - EXACT_TAIL;
    if (Tmain < 0) Tmain = 0;

    h = run_range<false>(h, xp, 0, Tmain, own_addr, vec_addr, w, Bj, wih);
    h = run_range<true >(h, xp, Tmain, T, own_addr, vec_addr, w, Bj, wih);

    // out[b] = sum_j h_j * fc_w[j] + fc_b
    float v = h * fc_w[j];
    v += __shfl_xor_sync(0xffffffffu, v, 4, 8);
    v += __shfl_xor_sync(0xffffffffu, v, 2, 8);
    v += __shfl_xor_sync(0xffffffffu, v, 1, 8);
    if (j == 0 && b_raw < B) out[b] = v + fc_b[0];
}

extern "C" void kernel_launch(void* const* d_in, const int* in_sizes, int n_in,
                              void* d_out, int out_size) {
    const float* x    = (const float*)d_in[0];
    const float* w_ih = (const float*)d_in[1];
    const float* w_hh = (const float*)d_in[2];
    const float* b_ih = (const float*)d_in[3];
    const float* b_hh = (const float*)d_in[4];
    const float* fc_w = (const float*)d_in[5];
    const float* fc_b = (const float*)d_in[6];
    float* out = (float*)d_out;

    int B = out_size;                 // O = 1
    int T = in_sizes[0] / B;          // I = 1
    int threads = B * 8;
    int grid = (threads + TBLOCK - 1) / TBLOCK;
    SmallRNN_kernel<<<grid, TBLOCK>>>(x, w_ih, w_hh, b_ih, b_hh, fc_w, fc_b,
                                      out, B, T);
}

// round 17
// speedup vs baseline: 1.1603x; 1.0448x over previous
#include <cuda_runtime.h>

// SmallRNN: h_t = tanh(x_t * w_ih^T + b_ih + h_{t-1} * w_hh^T + b_hh), out = h_T @ fc_w^T + fc_b
// Shapes: x [B=4096, T=2048, I=1], w_ih [8,1], w_hh [8,8], b_* [8], fc_w [1,8], fc_b [1]
//
// FINAL (best measured: 90.6us; reproduced 91.2 / 94.7us; rel_err 1.76e-7):
// 8 lanes per batch element (lane j owns h_j) — chain MUFU count = 1 (minimum).
// Exchange via shared memory: asm-pinned STS.32 -> 2x LDS.128 (broadcast,
// conflict-free); memory clobbers required — removing them or reshaping the
// body regresses the ptxas schedule (measured).
// Activation: tanh.approx.f32 for the first T-64 steps; exact ex2+rcp tanh for
// the last 64. The recurrence contracts (gamma ~ 0.5), so early approx error
// is suppressed below fp32 rounding by the exact tail (verified bit-stable).
// Eight structural variants measured slower: shuffle exchange (+53cyc/step),
// 2-lane / 1-thread layouts (MUFU spacing), lockstep & phase-offset pairing,
// clobber removal, tree reshaping, unroll-16 (reg pressure). The kernel sits
// at the dependency-chain floor (~84 cyc/step = LDS visibility ~35 + FMA tree
// 16 + MUFU 16 + latch/loop ~17); no throughput resource exceeds 32%.

#define TBLOCK 256
#define EXACT_TAIL 64

__device__ __forceinline__ float ex2f(float x) {
    float y; asm("ex2.approx.f32 %0, %1;" : "=f"(y) : "f"(x)); return y;
}
__device__ __forceinline__ float rcpf(float x) {
    float y; asm("rcp.approx.f32 %0, %1;" : "=f"(y) : "f"(x)); return y;
}
__device__ __forceinline__ float tanhf_approx(float x) {
    float y; asm("tanh.approx.f32 %0, %1;" : "=f"(y) : "f"(x)); return y;
}

template <bool EXACT>
__device__ __forceinline__ float rnn_step(float h, float xv,
                                          unsigned own_addr, unsigned vec_addr,
                                          const float w[8], float Bj, float wih) {
    // publish own h, then fetch the group's 8 values; asm volatile + memory
    // clobber pins ST->LD ordering (per-warp in-order smem LSU does the rest).
    asm volatile("st.shared.f32 [%0], %1;" :: "r"(own_addr), "f"(h) : "memory");
    float v0, v1, v2, v3, v4, v5, v6, v7;
    asm volatile("ld.shared.v4.f32 {%0,%1,%2,%3}, [%4];"
                 : "=f"(v0), "=f"(v1), "=f"(v2), "=f"(v3)
                 : "r"(vec_addr) : "memory");
    asm volatile("ld.shared.v4.f32 {%0,%1,%2,%3}, [%4];"
                 : "=f"(v4), "=f"(v5), "=f"(v6), "=f"(v7)
                 : "r"(vec_addr + 16u) : "memory");
    // 4-way split FMA tree, then combine; x-term and bias are off-chain
    float a = fmaf(xv, wih, Bj);
    a = fmaf(v0, w[0], a);
    float b = v1 * w[1];
    float cc = v2 * w[2];
    float d = v3 * w[3];
    a  = fmaf(v4, w[4], a);
    b  = fmaf(v5, w[5], b);
    cc = fmaf(v6, w[6], cc);
    d  = fmaf(v7, w[7], d);
    float s = (a + b) + (cc + d);
    if (EXACT) {
        const float c2 = 2.8853900817779268f; // 2*log2(e)
        float e = ex2f(c2 * s);
        float r = rcpf(e + 1.0f);
        return fmaf(-2.0f, r, 1.0f); // tanh(s) = 1 - 2*sigmoid(-2s)
    } else {
        return tanhf_approx(s);
    }
}

template <bool EXACT>
__device__ __forceinline__ float run_range(float h, const float* __restrict__ xp,
                                           int t0, int t1,
                                           unsigned own_addr, unsigned vec_addr,
                                           const float w[8], float Bj, float wih) {
    int span = t1 - t0;
    int Tm = span & ~7;
    const float* p = xp + t0;
    if (((unsigned long long)p & 15ull) == 0ull && Tm > 0) {
        float4 xa = *(const float4*)(p);
        float4 xb_ = *(const float4*)(p + 4);
        for (int t = 0; t < Tm; t += 8) {
            float4 xn0, xn1;
            if (t + 8 < Tm) {
                xn0 = *(const float4*)(p + t + 8);
                xn1 = *(const float4*)(p + t + 12);
            } else {
                xn0 = make_float4(0.f, 0.f, 0.f, 0.f);
                xn1 = xn0;
            }
            h = rnn_step<EXACT>(h, xa.x,  own_addr, vec_addr, w, Bj, wih);
            h = rnn_step<EXACT>(h, xa.y,  own_addr, vec_addr, w, Bj, wih);
            h = rnn_step<EXACT>(h, xa.z,  own_addr, vec_addr, w, Bj, wih);
            h = rnn_step<EXACT>(h, xa.w,  own_addr, vec_addr, w, Bj, wih);
            h = rnn_step<EXACT>(h, xb_.x, own_addr, vec_addr, w, Bj, wih);
            h = rnn_step<EXACT>(h, xb_.y, own_addr, vec_addr, w, Bj, wih);
            h = rnn_step<EXACT>(h, xb_.z, own_addr, vec_addr, w, Bj, wih);
            h = rnn_step<EXACT>(h, xb_.w, own_addr, vec_addr, w, Bj, wih);
            xa  = xn0;
            xb_ = xn1;
        }
    } else {
        Tm = 0;
    }
    for (int t = t0 + Tm; t < t1; t++) {
        h = rnn_step<EXACT>(h, xp[t], own_addr, vec_addr, w, Bj, wih);
    }
    return h;
}

__global__ void __launch_bounds__(TBLOCK)
SmallRNN_kernel(const float* __restrict__ x,
                const float* __restrict__ w_ih,
                const float* __restrict__ w_hh,
                const float* __restrict__ b_ih,
                const float* __restrict__ b_hh,
                const float* __restrict__ fc_w,
                const float* __restrict__ fc_b,
                float* __restrict__ out,
                int B, int T) {
    __shared__ float sh[TBLOCK];

    int tx = threadIdx.x;
    int gtid = blockIdx.x * TBLOCK + tx;
    int b_raw = gtid >> 3;     // batch element
    int j = gtid & 7;          // hidden unit owned by this lane
    int b = (b_raw < B) ? b_raw : (B - 1);  // keep lanes active

    unsigned own_addr = (unsigned)__cvta_generic_to_shared(sh + tx);
    unsigned vec_addr = (unsigned)__cvta_generic_to_shared(sh + (tx & ~7));

    float w[8];
#pragma unroll
    for (int k = 0; k < 8; k++) w[k] = w_hh[j * 8 + k];
    float Bj  = b_ih[j] + b_hh[j];
    float wih = w_ih[j];

    const float* xp = x + (size_t)b * (size_t)T;
    float h = 0.0f; // h0 = 0

    int Tmain = T - EXACT_TAIL;
    if (Tmain < 0) Tmain = 0;

    h = run_range<false>(h, xp, 0, Tmain, own_addr, vec_addr, w, Bj, wih);
    h = run_range<true >(h, xp, Tmain, T, own_addr, vec_addr, w, Bj, wih);

    // out[b] = sum_j h_j * fc_w[j] + fc_b
    float v = h * fc_w[j];
    v += __shfl_xor_sync(0xffffffffu, v, 4, 8);
    v += __shfl_xor_sync(0xffffffffu, v, 2, 8);
    v += __shfl_xor_sync(0xffffffffu, v, 1, 8);
    if (j == 0 && b_raw < B) out[b] = v + fc_b[0];
}

extern "C" void kernel_launch(void* const* d_in, const int* in_sizes, int n_in,
                              void* d_out, int out_size) {
    const float* x    = (const float*)d_in[0];
    const float* w_ih = (const float*)d_in[1];
    const float* w_hh = (const float*)d_in[2];
    const float* b_ih = (const float*)d_in[3];
    const float* b_hh = (const float*)d_in[4];
    const float* fc_w = (const float*)d_in[5];
    const float* fc_b = (const float*)d_in[6];
    float* out = (float*)d_out;

    int B = out_size;                 // O = 1
    int T = in_sizes[0] / B;          // I = 1
    int threads = B * 8;
    int grid = (threads + TBLOCK - 1) / TBLOCK;
    SmallRNN_kernel<<<grid, TBLOCK>>>(x, w_ih, w_hh, b_ih, b_hh, fc_w, fc_b,
                                      out, B, T);
}